// round 5
// baseline (speedup 1.0000x reference)
#include <cuda_runtime.h>
#include <math.h>

#define H 16
#define S 2048
#define D 128
#define M 4096
#define TOPK 16
#define TQ 64
#define TK 128
#define NC (M / TK)   // 32 chunks

// Scratch (device globals; cudaMalloc is forbidden)
__device__ float g_kn[H * M * D];   // 32 MB normalized key memories
__device__ float g_qn[H * S * D];   // 16 MB normalized queries

#define FMA_F32X2(d, a, b, c) \
    asm("fma.rn.f32x2 %0, %1, %2, %3;" : "=l"(d) : "l"(a), "l"(b), "l"(c))

// ---------------------------------------------------------------------------
// Row L2-normalization matching XLA:CPU rounding exactly:
//   acc = 0; for d: acc = fadd_rn(acc, fmul_rn(x_d, x_d));  (sequential, no FMA)
//   n = sqrt_rn(acc); dnm = max(n, 1e-6); out = fdiv_rn(x, dnm)
// One fused launch: blocks [0, HM/64) normalize kmem, rest normalize query.
// ---------------------------------------------------------------------------
__global__ __launch_bounds__(256)
void normalize_rows2(const float* __restrict__ kmem,
                     const float* __restrict__ query,
                     float* __restrict__ kn, float* __restrict__ qn,
                     int kblocks) {
    __shared__ float rows[64 * 129];
    __shared__ float rnorm[64];
    const int tid = threadIdx.x;
    const float* src;
    float* dst;
    size_t base;
    if ((int)blockIdx.x < kblocks) {
        src = kmem; dst = kn; base = (size_t)blockIdx.x * 64 * D;
    } else {
        src = query; dst = qn; base = (size_t)(blockIdx.x - kblocks) * 64 * D;
    }

#pragma unroll
    for (int i = 0; i < 32; i++) {
        int idx = i * 256 + tid;
        int r = idx >> 7;
        int d = idx & 127;
        rows[r * 129 + d] = src[base + (size_t)r * D + d];
    }
    __syncthreads();

    if (tid < 64) {
        const float* rp = rows + tid * 129;
        float acc = 0.f;
#pragma unroll 8
        for (int d = 0; d < D; d++)
            acc = __fadd_rn(acc, __fmul_rn(rp[d], rp[d]));
        float n = __fsqrt_rn(acc);
        rnorm[tid] = fmaxf(n, 1e-6f);
    }
    __syncthreads();

#pragma unroll
    for (int i = 0; i < 32; i++) {
        int idx = i * 256 + tid;
        int r = idx >> 7;
        int d = idx & 127;
        dst[base + (size_t)r * D + d] = __fdiv_rn(rows[r * 129 + d], rnorm[r]);
    }
}

// ---------------------------------------------------------------------------
// Main fused kernel, per (head, 64-query tile). 256 threads = 64 q x 4 parts,
// each part owns 32 keys per 128-key chunk (32 chunks over M=4096).
//   phase 1: f32x2 sims (per-(q,k) single sequential IEEE FMA chain over d),
//            per-part register top-16
//   phase 2: merge 4x16 -> exact top-16 desc, lowest-index tie-break
//   phase 3: weighted value gather (descending) + gated combine
// ---------------------------------------------------------------------------
__global__ __launch_bounds__(256, 1)
void praxis_main(const float* __restrict__ outputs,
                 const float* __restrict__ gate,
                 const float* __restrict__ vmem,
                 float* __restrict__ out) {
    extern __shared__ float smem[];
    float* sQ = smem;                   // [D][TQ]  32 KB, floats [0, 8192)
    float* sK = smem + 8192;            // [D][TK]  64 KB, floats [8192, 24576)
    // post-loop aliases of the sK region (guarded by __syncthreads):
    float* candS = smem + 8192;                       // [64][65] floats
    int*   candI = (int*)(smem + 8192 + 64 * 65);     // [64][65] ints
    float* finS  = (float*)((char*)smem + 98304);     // [64][16]
    int*   finI  = (int*)((char*)smem + 98304 + 4096);

    const int h     = blockIdx.y;
    const int qtile = blockIdx.x;
    const int tid   = threadIdx.x;
    const int q     = tid & 63;
    const int part  = tid >> 6;

    // ---- Load query tile transposed [d][q] ----
    const float4* qsrc = reinterpret_cast<const float4*>(
        g_qn + ((size_t)h * S + (size_t)qtile * TQ) * D);
#pragma unroll
    for (int i = 0; i < 8; i++) {
        int idx = i * 256 + tid;
        int r   = idx & 63;
        int c4  = idx >> 6;
        float4 v = qsrc[r * (D / 4) + c4];
        sQ[(c4 * 4 + 0) * TQ + r] = v.x;
        sQ[(c4 * 4 + 1) * TQ + r] = v.y;
        sQ[(c4 * 4 + 2) * TQ + r] = v.z;
        sQ[(c4 * 4 + 3) * TQ + r] = v.w;
    }

    // ---- Register top-16 state ----
    float ls[TOPK]; int li[TOPK];
#pragma unroll
    for (int j = 0; j < TOPK; j++) { ls[j] = -INFINITY; li[j] = 0; }
    float lmin = -INFINITY;

    const float4* ksrc = reinterpret_cast<const float4*>(g_kn + (size_t)h * M * D);

    for (int c = 0; c < NC; c++) {
        __syncthreads();
        // Load 128-key chunk transposed [d][key]: 16 float4 per thread
#pragma unroll
        for (int i = 0; i < 16; i++) {
            int idx = i * 256 + tid;
            int r   = idx & 127;           // key within chunk
            int c4  = idx >> 7;            // float4 column (0..31)
            float4 v = ksrc[(size_t)(c * TK + r) * (D / 4) + c4];
            sK[(c4 * 4 + 0) * TK + r] = v.x;
            sK[(c4 * 4 + 1) * TK + r] = v.y;
            sK[(c4 * 4 + 2) * TK + r] = v.z;
            sK[(c4 * 4 + 3) * TK + r] = v.w;
        }
        __syncthreads();

        const ulonglong2* sk8 = reinterpret_cast<const ulonglong2*>(sK);
        unsigned long long acc[16];
#pragma unroll
        for (int t = 0; t < 16; t++) acc[t] = 0ull;   // packed (+0.f, +0.f)

#pragma unroll 2
        for (int d = 0; d < D; d++) {
            float qv = sQ[d * TQ + q];
            unsigned long long q2;
            asm("mov.b64 %0, {%1, %1};" : "=l"(q2) : "f"(qv));
            // 8 x 16B broadcast loads cover this part's 32 keys
            ulonglong2 k0 = sk8[d * (TK / 4) + part * 8 + 0];
            ulonglong2 k1 = sk8[d * (TK / 4) + part * 8 + 1];
            ulonglong2 k2 = sk8[d * (TK / 4) + part * 8 + 2];
            ulonglong2 k3 = sk8[d * (TK / 4) + part * 8 + 3];
            ulonglong2 k4 = sk8[d * (TK / 4) + part * 8 + 4];
            ulonglong2 k5 = sk8[d * (TK / 4) + part * 8 + 5];
            ulonglong2 k6 = sk8[d * (TK / 4) + part * 8 + 6];
            ulonglong2 k7 = sk8[d * (TK / 4) + part * 8 + 7];
            FMA_F32X2(acc[0],  q2, k0.x, acc[0]);
            FMA_F32X2(acc[1],  q2, k0.y, acc[1]);
            FMA_F32X2(acc[2],  q2, k1.x, acc[2]);
            FMA_F32X2(acc[3],  q2, k1.y, acc[3]);
            FMA_F32X2(acc[4],  q2, k2.x, acc[4]);
            FMA_F32X2(acc[5],  q2, k2.y, acc[5]);
            FMA_F32X2(acc[6],  q2, k3.x, acc[6]);
            FMA_F32X2(acc[7],  q2, k3.y, acc[7]);
            FMA_F32X2(acc[8],  q2, k4.x, acc[8]);
            FMA_F32X2(acc[9],  q2, k4.y, acc[9]);
            FMA_F32X2(acc[10], q2, k5.x, acc[10]);
            FMA_F32X2(acc[11], q2, k5.y, acc[11]);
            FMA_F32X2(acc[12], q2, k6.x, acc[12]);
            FMA_F32X2(acc[13], q2, k6.y, acc[13]);
            FMA_F32X2(acc[14], q2, k7.x, acc[14]);
            FMA_F32X2(acc[15], q2, k7.y, acc[15]);
        }

        // Running top-16 update over this chunk's 32 keys
        int kbase = c * TK + part * 32;
#pragma unroll
        for (int t = 0; t < 16; t++) {
            float s0, s1;
            asm("mov.b64 {%0, %1}, %2;" : "=f"(s0), "=f"(s1) : "l"(acc[t]));
            if (s0 > lmin) {
                bool done = false;
#pragma unroll
                for (int j = 0; j < TOPK; j++)
                    if (!done && ls[j] == lmin) { ls[j] = s0; li[j] = kbase + 2 * t; done = true; }
                lmin = ls[0];
#pragma unroll
                for (int j = 1; j < TOPK; j++) lmin = fminf(lmin, ls[j]);
            }
            if (s1 > lmin) {
                bool done = false;
#pragma unroll
                for (int j = 0; j < TOPK; j++)
                    if (!done && ls[j] == lmin) { ls[j] = s1; li[j] = kbase + 2 * t + 1; done = true; }
                lmin = ls[0];
#pragma unroll
                for (int j = 1; j < TOPK; j++) lmin = fminf(lmin, ls[j]);
            }
        }
    }
    __syncthreads();  // retire sK reads before alias writes

    // ---- Dump per-part candidates (stride 65 -> conflict-free) ----
#pragma unroll
    for (int j = 0; j < TOPK; j++) {
        candS[q * 65 + part * 16 + j] = ls[j];
        candI[q * 65 + part * 16 + j] = li[j];
    }
    __syncthreads();

    // ---- Merge: exact top-16 of 64, descending, lowest-index tie-break ----
    if (tid < 64) {
        int qq = tid;
        for (int p = 0; p < TOPK; p++) {
            float best = -INFINITY; int bj = 0; int bi = 0x7fffffff;
            for (int j = 0; j < 64; j++) {
                float v = candS[qq * 65 + j];
                int idx = candI[qq * 65 + j];
                if (v > best || (v == best && idx < bi)) { best = v; bj = j; bi = idx; }
            }
            finS[qq * TOPK + p] = best;
            finI[qq * TOPK + p] = bi;
            candS[qq * 65 + bj] = -INFINITY;
        }
    }
    __syncthreads();

    // ---- Weighted value gather (descending order == reference) + combine ----
    {
        int oq   = tid >> 2;
        int dseg = tid & 3;
        float4 a4[8];
#pragma unroll
        for (int j = 0; j < 8; j++) a4[j] = make_float4(0.f, 0.f, 0.f, 0.f);
        const float4* vm4 = reinterpret_cast<const float4*>(vmem + (size_t)h * M * D);
        for (int n = 0; n < TOPK; n++) {
            float w  = finS[oq * TOPK + n];
            int   ki = finI[oq * TOPK + n];
            const float4* row = vm4 + (size_t)ki * (D / 4) + dseg * 8;
#pragma unroll
            for (int j = 0; j < 8; j++) {
                float4 v = row[j];
                a4[j].x = __fmaf_rn(w, v.x, a4[j].x);
                a4[j].y = __fmaf_rn(w, v.y, a4[j].y);
                a4[j].z = __fmaf_rn(w, v.z, a4[j].z);
                a4[j].w = __fmaf_rn(w, v.w, a4[j].w);
            }
        }
        float gv = gate[h];
        float g  = __fdiv_rn(1.f, __fadd_rn(1.f, expf(-gv)));
        float og = __fsub_rn(1.f, g);
        size_t obase = (((size_t)h * S + (size_t)qtile * TQ + oq) * D) + (size_t)dseg * 32;
        const float4* o4 = reinterpret_cast<const float4*>(outputs + obase);
        float4*       w4 = reinterpret_cast<float4*>(out + obase);
#pragma unroll
        for (int j = 0; j < 8; j++) {
            float4 o = o4[j];
            float4 r;
            r.x = __fadd_rn(__fmul_rn(g, a4[j].x), __fmul_rn(og, o.x));
            r.y = __fadd_rn(__fmul_rn(g, a4[j].y), __fmul_rn(og, o.y));
            r.z = __fadd_rn(__fmul_rn(g, a4[j].z), __fmul_rn(og, o.z));
            r.w = __fadd_rn(__fmul_rn(g, a4[j].w), __fmul_rn(og, o.w));
            w4[j] = r;
        }
    }
}

// ---------------------------------------------------------------------------
// inputs: 0 inputs, 1 query, 2 key, 3 value, 4 outputs, 5 gate,
//         6 key_memories, 7 value_memories
// ---------------------------------------------------------------------------
extern "C" void kernel_launch(void* const* d_in, const int* in_sizes, int n_in,
                              void* d_out, int out_size) {
    (void)in_sizes; (void)n_in; (void)out_size;
    const float* query   = (const float*)d_in[1];
    const float* outputs = (const float*)d_in[4];
    const float* gate    = (const float*)d_in[5];
    const float* kmem    = (const float*)d_in[6];
    const float* vmem    = (const float*)d_in[7];
    float* out = (float*)d_out;

    float* kn_ptr = nullptr;
    float* qn_ptr = nullptr;
    cudaGetSymbolAddress((void**)&kn_ptr, g_kn);
    cudaGetSymbolAddress((void**)&qn_ptr, g_qn);

    const int kblocks = (H * M) / 64;   // 1024
    const int qblocks = (H * S) / 64;   // 512
    normalize_rows2<<<kblocks + qblocks, 256>>>(kmem, query, kn_ptr, qn_ptr, kblocks);

    const int smem_bytes = 98304 + 8192;   // tiles + fin = 106496
    static int configured = 0;
    if (!configured) {
        cudaFuncSetAttribute(praxis_main,
                             cudaFuncAttributeMaxDynamicSharedMemorySize, smem_bytes);
        configured = 1;
    }
    dim3 grid(S / TQ, H);
    praxis_main<<<grid, 256, smem_bytes>>>(outputs, gate, vmem, out);
}

// round 7
// speedup vs baseline: 1.3882x; 1.3882x over previous
#include <cuda_runtime.h>
#include <cuda_bf16.h>
#include <math.h>
#include <stdint.h>

#define H 16
#define S 2048
#define D 128
#define M 4096
#define TOPK 16
#define QT 128            // queries per CTA
#define CK 64             // keys per chunk
#define NCH (M / CK)      // 64 chunks
#define NKEEP 20          // per-lane candidates per key-half
#define NCAND 40          // per-query candidates
#define CSTR 41           // padded candidate stride

// Scratch (device globals; cudaMalloc is forbidden)
__device__ __align__(16) float          g_kn [H * M * D];
__device__ __align__(16) float          g_qn [H * S * D];
__device__ __align__(16) __nv_bfloat16  g_knb[H * M * D];
__device__ __align__(16) __nv_bfloat16  g_qnb[H * S * D];

// ---------------- smem layout (bytes) ----------------
#define LDT 136                    // bf16 row stride (128 + 8 pad) = 272 B
#define SM_A   0                   // A tile 128 x LDT bf16 = 34816
#define SM_B0  34816               // key buf 0: 64 x LDT bf16 = 17408
#define SM_B1  52224               // key buf 1
#define SM_SC  69632               // scores: 8 warps x 16 x 66 f32 = 33792
#define SM_TOTAL 103424
// aliases after main loop:
#define SM_FS  0                   // finS [128][16] f32 (8192)
#define SM_FI  8192                // finI [128][16] i32 (8192)
#define SM_CI  34816               // candI [128][41] i32 (20992)
#define SM_CSC 55808               // candS [128][41] f32 (20992)

__device__ __forceinline__ uint32_t smem_u32(const void* p) {
    uint32_t a;
    asm("{ .reg .u64 t; cvta.to.shared.u64 t, %1; cvt.u32.u64 %0, t; }" : "=r"(a) : "l"(p));
    return a;
}
#define CP_ASYNC16(dst, src) \
    asm volatile("cp.async.cg.shared.global [%0], [%1], 16;" :: "r"(dst), "l"(src))
#define CP_COMMIT() asm volatile("cp.async.commit_group;" ::: "memory")
#define CP_WAIT(n)  asm volatile("cp.async.wait_group %0;" :: "n"(n) : "memory")

#define LDMATRIX_X4(r0, r1, r2, r3, a) \
    asm volatile("ldmatrix.sync.aligned.m8n8.x4.shared.b16 {%0,%1,%2,%3}, [%4];" \
                 : "=r"(r0), "=r"(r1), "=r"(r2), "=r"(r3) : "r"(a))

#define MMA16816(c0, c1, c2, c3, a0, a1, a2, a3, b0, b1) \
    asm volatile("mma.sync.aligned.m16n8k16.row.col.f32.bf16.bf16.f32 " \
                 "{%0,%1,%2,%3}, {%4,%5,%6,%7}, {%8,%9}, {%0,%1,%2,%3};" \
                 : "+f"(c0), "+f"(c1), "+f"(c2), "+f"(c3) \
                 : "r"(a0), "r"(a1), "r"(a2), "r"(a3), "r"(b0), "r"(b1))

// monotone pack: order-preserving float bits | 12-bit key index in low bits
__device__ __forceinline__ uint32_t packSI(float s, uint32_t idx) {
    uint32_t b = __float_as_uint(s);
    b = (b & 0x80000000u) ? ~b : (b | 0x80000000u);
    return (b & 0xFFFFF000u) | idx;
}

// ---------------------------------------------------------------------------
// Exact row L2-normalization (XLA:CPU rounding: sequential mul/add, no FMA)
// emits fp32 + bf16 copies. Blocks [0, kblocks) -> kmem, rest -> query.
// ---------------------------------------------------------------------------
__global__ __launch_bounds__(256)
void normalize_rows2(const float* __restrict__ kmem, const float* __restrict__ query,
                     float* __restrict__ kn, float* __restrict__ qn,
                     __nv_bfloat16* __restrict__ knb, __nv_bfloat16* __restrict__ qnb,
                     int kblocks) {
    __shared__ float rows[64 * 129];
    __shared__ float rnorm[64];
    const int tid = threadIdx.x;
    const float* src; float* dst; __nv_bfloat16* dstb; size_t base;
    if ((int)blockIdx.x < kblocks) {
        src = kmem; dst = kn; dstb = knb; base = (size_t)blockIdx.x * 64 * D;
    } else {
        src = query; dst = qn; dstb = qnb; base = (size_t)(blockIdx.x - kblocks) * 64 * D;
    }
#pragma unroll
    for (int i = 0; i < 32; i++) {
        int idx = i * 256 + tid; int r = idx >> 7; int d = idx & 127;
        rows[r * 129 + d] = src[base + (size_t)r * D + d];
    }
    __syncthreads();
    if (tid < 64) {
        const float* rp = rows + tid * 129;
        float acc = 0.f;
#pragma unroll 8
        for (int d = 0; d < D; d++) acc = __fadd_rn(acc, __fmul_rn(rp[d], rp[d]));
        rnorm[tid] = fmaxf(__fsqrt_rn(acc), 1e-6f);
    }
    __syncthreads();
#pragma unroll
    for (int i = 0; i < 32; i++) {
        int idx = i * 256 + tid; int r = idx >> 7; int d = idx & 127;
        float v = __fdiv_rn(rows[r * 129 + d], rnorm[r]);
        dst[base + (size_t)r * D + d]  = v;
        dstb[base + (size_t)r * D + d] = __float2bfloat16(v);
    }
}

// ---------------------------------------------------------------------------
// Main kernel: per (head, 128-query tile).
//   phase 1: bf16 mma.sync sims, per-lane packed top-20 per key-half
//   phase 2: exact fp32 sequential-FMA rescore of 40 candidates/query
//   phase 3: exact merge top-16 desc (lowest-index ties)
//   phase 4: weighted gather (descending) + gated combine
// ---------------------------------------------------------------------------
__global__ __launch_bounds__(256, 2)
void tc_main(const float* __restrict__ outputs, const float* __restrict__ gate,
             const float* __restrict__ vmem, float* __restrict__ out) {
    extern __shared__ char sm[];
    const uint32_t sb = smem_u32(sm);

    const int tid  = threadIdx.x;
    const int wid  = tid >> 5;
    const int lane = tid & 31;
    const int h     = blockIdx.y;
    const int qtile = blockIdx.x;
    const int qbase = qtile * QT;

    // ---- stage A (query tile) bf16 into smem, row stride LDT ----
    {
        const __nv_bfloat16* qb = g_qnb + ((size_t)h * S + qbase) * D;
#pragma unroll
        for (int i = 0; i < 8; i++) {
            int idx = i * 256 + tid;            // 2048 16B groups
            int row = idx >> 4, g16 = idx & 15;
            uint4 v = *reinterpret_cast<const uint4*>(qb + (size_t)row * D + g16 * 8);
            *reinterpret_cast<uint4*>(sm + SM_A + row * (LDT * 2) + g16 * 16) = v;
        }
    }

    const __nv_bfloat16* kb = g_knb + (size_t)h * M * D;
    // cp.async key-chunk loader
    auto load_chunk = [&](int c) {
        const __nv_bfloat16* kc = kb + (size_t)c * CK * D;
        uint32_t bs = sb + ((c & 1) ? SM_B1 : SM_B0);
#pragma unroll
        for (int i = 0; i < 4; i++) {
            int idx = i * 256 + tid;            // 1024 16B groups
            int row = idx >> 4, g16 = idx & 15;
            CP_ASYNC16(bs + row * (LDT * 2) + g16 * 16,
                       kc + (size_t)row * D + g16 * 8);
        }
    };

    // per-lane ldmatrix base offsets
    const int rA = wid * 16 + (lane & 7) + ((lane >> 3) & 1) * 8;
    const uint32_t baseA = sb + SM_A + rA * (LDT * 2) + ((lane >> 4) & 1) * 16;
    uint32_t baseB[4];
#pragma unroll
    for (int p = 0; p < 4; p++) {
        int key = p * 16 + ((lane >> 4) & 1) * 8 + (lane & 7);
        baseB[p] = key * (LDT * 2) + ((lane >> 3) & 1) * 16;
    }
    // score staging: warp region [16][66] f32
    const uint32_t scW = sb + SM_SC + wid * (16 * 66 * 4);
    const int g = lane >> 2, t = lane & 3;
    const uint32_t stLo = scW + (g * 66 + 2 * t) * 4;         // +nt*32B
    const uint32_t stHi = scW + ((g + 8) * 66 + 2 * t) * 4;
    const int rr = lane >> 1, hh = lane & 1;                   // read row/half
    const uint32_t rdB = scW + (rr * 66 + hh * 32) * 4;

    // packed top-NKEEP state
    uint32_t ls[NKEEP]; uint32_t lmin = 0;
#pragma unroll
    for (int j = 0; j < NKEEP; j++) ls[j] = 0;

    load_chunk(0); CP_COMMIT();

    for (int c = 0; c < NCH; c++) {
        if (c < NCH - 1) { load_chunk(c + 1); CP_COMMIT(); CP_WAIT(1); }
        else             { CP_WAIT(0); }
        __syncthreads();

        const uint32_t bbuf = sb + ((c & 1) ? SM_B1 : SM_B0);
        float acc[8][4];
#pragma unroll
        for (int nt = 0; nt < 8; nt++)
#pragma unroll
            for (int j = 0; j < 4; j++) acc[nt][j] = 0.f;

#pragma unroll
        for (int kk = 0; kk < 8; kk++) {
            uint32_t a0, a1, a2, a3;
            LDMATRIX_X4(a0, a1, a2, a3, baseA + kk * 32);
#pragma unroll
            for (int p = 0; p < 4; p++) {
                uint32_t b0, b1, b2, b3;
                LDMATRIX_X4(b0, b1, b2, b3, bbuf + baseB[p] + kk * 32);
                MMA16816(acc[2 * p][0], acc[2 * p][1], acc[2 * p][2], acc[2 * p][3],
                         a0, a1, a2, a3, b0, b1);
                MMA16816(acc[2 * p + 1][0], acc[2 * p + 1][1], acc[2 * p + 1][2], acc[2 * p + 1][3],
                         a0, a1, a2, a3, b2, b3);
            }
        }

        // stage scores [16 q][64 k] to smem
#pragma unroll
        for (int nt = 0; nt < 8; nt++) {
            *reinterpret_cast<float2*>(sm + (stLo - sb) + nt * 32) =
                make_float2(acc[nt][0], acc[nt][1]);
            *reinterpret_cast<float2*>(sm + (stHi - sb) + nt * 32) =
                make_float2(acc[nt][2], acc[nt][3]);
        }
        __syncwarp();

        // per-lane running top-NKEEP over its 32 keys (row rr, half hh)
        const int kb0 = c * CK + hh * 32;
#pragma unroll
        for (int j = 0; j < 16; j++) {
            float2 sv = *reinterpret_cast<const float2*>(sm + (rdB - sb) + j * 8);
            uint32_t u0 = packSI(sv.x, (uint32_t)(kb0 + 2 * j));
            uint32_t u1 = packSI(sv.y, (uint32_t)(kb0 + 2 * j + 1));
            if (u0 > lmin) {
                bool done = false;
#pragma unroll
                for (int q2 = 0; q2 < NKEEP; q2++)
                    if (!done && ls[q2] == lmin) { ls[q2] = u0; done = true; }
                lmin = ls[0];
#pragma unroll
                for (int q2 = 1; q2 < NKEEP; q2++) lmin = min(lmin, ls[q2]);
            }
            if (u1 > lmin) {
                bool done = false;
#pragma unroll
                for (int q2 = 0; q2 < NKEEP; q2++)
                    if (!done && ls[q2] == lmin) { ls[q2] = u1; done = true; }
                lmin = ls[0];
#pragma unroll
                for (int q2 = 1; q2 < NKEEP; q2++) lmin = min(lmin, ls[q2]);
            }
        }
        __syncthreads();
    }

    // ---- dump candidate indices (40 per query) ----
    int* candI = (int*)(sm + SM_CI);
    float* candS = (float*)(sm + SM_CSC);
    {
        int q = wid * 16 + rr;
#pragma unroll
        for (int j = 0; j < NKEEP; j++)
            candI[q * CSTR + hh * NKEEP + j] = (int)(ls[j] & 0xFFFu);
    }
    __syncthreads();

    // ---- exact fp32 rescore: sequential FMA chain over d=0..127 ----
    {
        const int qq = tid >> 1;
        const int j0 = (tid & 1) * NKEEP;
        const float4* qrow = reinterpret_cast<const float4*>(
            g_qn + ((size_t)h * S + qbase + qq) * D);
        const float* knh = g_kn + (size_t)h * M * D;
#pragma unroll
        for (int grp = 0; grp < 5; grp++) {
            const float4* kr[4];
            float a0 = 0.f, a1 = 0.f, a2 = 0.f, a3 = 0.f;
#pragma unroll
            for (int i = 0; i < 4; i++) {
                int ki = candI[qq * CSTR + j0 + grp * 4 + i];
                kr[i] = reinterpret_cast<const float4*>(knh + (size_t)ki * D);
            }
#pragma unroll 4
            for (int v = 0; v < 32; v++) {
                float4 qv = qrow[v];
                float4 k0 = kr[0][v], k1 = kr[1][v], k2 = kr[2][v], k3 = kr[3][v];
                a0 = __fmaf_rn(qv.x, k0.x, a0); a0 = __fmaf_rn(qv.y, k0.y, a0);
                a0 = __fmaf_rn(qv.z, k0.z, a0); a0 = __fmaf_rn(qv.w, k0.w, a0);
                a1 = __fmaf_rn(qv.x, k1.x, a1); a1 = __fmaf_rn(qv.y, k1.y, a1);
                a1 = __fmaf_rn(qv.z, k1.z, a1); a1 = __fmaf_rn(qv.w, k1.w, a1);
                a2 = __fmaf_rn(qv.x, k2.x, a2); a2 = __fmaf_rn(qv.y, k2.y, a2);
                a2 = __fmaf_rn(qv.z, k2.z, a2); a2 = __fmaf_rn(qv.w, k2.w, a2);
                a3 = __fmaf_rn(qv.x, k3.x, a3); a3 = __fmaf_rn(qv.y, k3.y, a3);
                a3 = __fmaf_rn(qv.z, k3.z, a3); a3 = __fmaf_rn(qv.w, k3.w, a3);
            }
            candS[qq * CSTR + j0 + grp * 4 + 0] = a0;
            candS[qq * CSTR + j0 + grp * 4 + 1] = a1;
            candS[qq * CSTR + j0 + grp * 4 + 2] = a2;
            candS[qq * CSTR + j0 + grp * 4 + 3] = a3;
        }
    }
    __syncthreads();

    // ---- exact merge: top-16 of 40, descending, lowest-index tie-break ----
    float* finS = (float*)(sm + SM_FS);
    int*   finI = (int*)(sm + SM_FI);
    if (tid < QT) {
        int qq = tid;
        for (int p = 0; p < TOPK; p++) {
            float best = -INFINITY; int bj = 0; int bi = 0x7fffffff;
            for (int j = 0; j < NCAND; j++) {
                float v = candS[qq * CSTR + j];
                int idx = candI[qq * CSTR + j];
                if (v > best || (v == best && idx < bi)) { best = v; bj = j; bi = idx; }
            }
            finS[qq * TOPK + p] = best;
            finI[qq * TOPK + p] = bi;
            candS[qq * CSTR + bj] = -INFINITY;
        }
    }
    __syncthreads();

    // ---- weighted value gather (descending) + gated combine ----
    {
        const int oq = tid >> 1;
        const int dh = tid & 1;
        float4 a4[16];
#pragma unroll
        for (int j = 0; j < 16; j++) a4[j] = make_float4(0.f, 0.f, 0.f, 0.f);
        const float4* vm4 = reinterpret_cast<const float4*>(vmem + (size_t)h * M * D);
        for (int n = 0; n < TOPK; n++) {
            float w  = finS[oq * TOPK + n];
            int   ki = finI[oq * TOPK + n];
            const float4* row = vm4 + (size_t)ki * (D / 4) + dh * 16;
#pragma unroll
            for (int j = 0; j < 16; j++) {
                float4 v = row[j];
                a4[j].x = __fmaf_rn(w, v.x, a4[j].x);
                a4[j].y = __fmaf_rn(w, v.y, a4[j].y);
                a4[j].z = __fmaf_rn(w, v.z, a4[j].z);
                a4[j].w = __fmaf_rn(w, v.w, a4[j].w);
            }
        }
        float gv = gate[h];
        float gg = __fdiv_rn(1.f, __fadd_rn(1.f, expf(-gv)));
        float og = __fsub_rn(1.f, gg);
        size_t ob = (((size_t)h * S + qbase + oq) * D) + (size_t)dh * 64;
        const float4* o4 = reinterpret_cast<const float4*>(outputs + ob);
        float4*       w4 = reinterpret_cast<float4*>(out + ob);
#pragma unroll
        for (int j = 0; j < 16; j++) {
            float4 o = o4[j];
            float4 r;
            r.x = __fadd_rn(__fmul_rn(gg, a4[j].x), __fmul_rn(og, o.x));
            r.y = __fadd_rn(__fmul_rn(gg, a4[j].y), __fmul_rn(og, o.y));
            r.z = __fadd_rn(__fmul_rn(gg, a4[j].z), __fmul_rn(og, o.z));
            r.w = __fadd_rn(__fmul_rn(gg, a4[j].w), __fmul_rn(og, o.w));
            w4[j] = r;
        }
    }
}

// ---------------------------------------------------------------------------
// inputs: 0 inputs, 1 query, 2 key, 3 value, 4 outputs, 5 gate,
//         6 key_memories, 7 value_memories
// ---------------------------------------------------------------------------
extern "C" void kernel_launch(void* const* d_in, const int* in_sizes, int n_in,
                              void* d_out, int out_size) {
    (void)in_sizes; (void)n_in; (void)out_size;
    const float* query   = (const float*)d_in[1];
    const float* outputs = (const float*)d_in[4];
    const float* gate    = (const float*)d_in[5];
    const float* kmem    = (const float*)d_in[6];
    const float* vmem    = (const float*)d_in[7];
    float* out = (float*)d_out;

    float *kn_p, *qn_p; __nv_bfloat16 *knb_p, *qnb_p;
    cudaGetSymbolAddress((void**)&kn_p, g_kn);
    cudaGetSymbolAddress((void**)&qn_p, g_qn);
    cudaGetSymbolAddress((void**)&knb_p, g_knb);
    cudaGetSymbolAddress((void**)&qnb_p, g_qnb);

    const int kblocks = (H * M) / 64;   // 1024
    const int qblocks = (H * S) / 64;   // 512
    normalize_rows2<<<kblocks + qblocks, 256>>>(kmem, query, kn_p, qn_p, knb_p, qnb_p, kblocks);

    static int configured = 0;
    if (!configured) {
        cudaFuncSetAttribute(tc_main, cudaFuncAttributeMaxDynamicSharedMemorySize, SM_TOTAL);
        configured = 1;
    }
    dim3 grid(S / QT, H);   // 16 x 16 = 256 CTAs
    tc_main<<<grid, 256, SM_TOTAL>>>(outputs, gate, vmem, out);
}